// round 7
// baseline (speedup 1.0000x reference)
#include <cuda_runtime.h>

// EMA alpha=0.2; out[i] = e_{idx}, idx = max(len[i],1)-1.
// 64-tap trailing window (tail weight 0.8^63 ~ 8e-7 << 1e-3 threshold);
// rows with idx < 64 computed exactly from x_0.
//
// Structure (R7): 2-lane row groups, 16 rows per warp -> 1024 warps total.
// Block = 64 threads (2 warps, 32 rows), grid = 512 CTAs -> at most
// ceil(512/148)=4 CTAs = 8 warps per SM (R6 straggler SMs carried 16).
// Each lane issues EIGHT independent aligned LDG.128 (float4): lane sub
// owns float4 chunks {sub, sub+2, ..., sub+14} of the 64-float window.
// Window start aligned up to 4 (keeps s >= n-63), clamped to [0, T-64].

#define LOG2_08 (-0.32192809488736234787f)  // log2(0.8)
#define INV08_8 (5.9604644775390625f)       // 0.8^-8 = 1.25^8

__global__ void __launch_bounds__(64)
ema_last_kernel(const float* __restrict__ x,
                const int* __restrict__ valid_len,
                float* __restrict__ out,
                int B, int T)
{
    int warp = (int)((blockIdx.x * blockDim.x + threadIdx.x) >> 5);
    int lane = threadIdx.x & 31;
    int sub  = lane & 1;                 // lane within 2-lane row group
    int row  = warp * 16 + (lane >> 1);
    if (row >= B) return;

    int len = valid_len[row];
    int n   = (len > 1 ? len : 1) - 1;   // target index idx = L-1

    // Aligned window start: s in [n-63, n-60] (or 0), 4-aligned, in-row.
    int s = n - 63;
    s = (s > 0) ? ((s + 3) & ~3) : 0;
    if (s > T - 64) s = T - 64;

    const float4* p = reinterpret_cast<const float4*>(x + (size_t)row * (size_t)T + s);

    // Eight independent loads issue back-to-back (MLP=8).
    float4 v[8];
#pragma unroll
    for (int k = 0; k < 8; ++k)
        v[k] = p[sub + 2 * k];

    int   j0 = s + 4 * sub;              // global index of v[0].x
    // base weight of v[0].x: 0.2 * 0.8^(n - j0)
    float wb = 0.2f * exp2f((float)(n - j0) * LOG2_08);

    float acc = 0.0f;
#pragma unroll
    for (int k = 0; k < 8; ++k) {
        int j = j0 + 8 * k;              // global index of v[k].x
        float w0 = wb;
        float w1 = wb * 1.25f;
        float w2 = wb * 1.5625f;
        float w3 = wb * 1.953125f;

        // seed tap (global index 0) has coefficient 0.8^n = 5 * (0.2*0.8^n).
        // Only reachable in chunk 0 (j >= 8k otherwise); compiler elides rest.
        if (j + 0 == 0) w0 *= 5.0f;
        // taps beyond n contribute nothing
        if (j + 0 > n) w0 = 0.0f;
        if (j + 1 > n) w1 = 0.0f;
        if (j + 2 > n) w2 = 0.0f;
        if (j + 3 > n) w3 = 0.0f;

        acc = fmaf(w0, v[k].x, acc);
        acc = fmaf(w1, v[k].y, acc);
        acc = fmaf(w2, v[k].z, acc);
        acc = fmaf(w3, v[k].w, acc);

        wb *= INV08_8;                   // advance base weight by 8 taps
    }

    // reduce over the 2-lane group
    acc += __shfl_xor_sync(0xffffffffu, acc, 1);

    if (sub == 0) out[row] = acc;
}

extern "C" void kernel_launch(void* const* d_in, const int* in_sizes, int n_in,
                              void* d_out, int out_size)
{
    const float* pop_history = (const float*)d_in[0];
    const int*   valid_len   = (const int*)d_in[1];
    float*       out         = (float*)d_out;

    int B = in_sizes[1];               // 16384
    int T = in_sizes[0] / in_sizes[1]; // 2048

    int threads = 64;                  // 2 warps = 32 rows per block
    int rows_per_block = (threads / 32) * 16;
    int blocks = (B + rows_per_block - 1) / rows_per_block;   // 512
    ema_last_kernel<<<blocks, threads>>>(pop_history, valid_len, out, B, T);
}